// round 3
// baseline (speedup 1.0000x reference)
#include <cuda_runtime.h>
#include <math.h>

// Problem constants (fixed by setup_inputs)
#define Bc   2
#define Tc   2048
#define Sc   2048
#define Ec   1024
#define Hc   16
#define HDc  64
#define MROWS (Bc*Tc)          // 4096
#define QSCALE 0.125f          // 64^-0.5

// Scratch (allocation-free: __device__ globals)
__device__ float g_q[(size_t)Bc*Tc*Ec];                 // 16 MB  [B,T,H,HD]
__device__ float g_k[(size_t)Bc*Sc*Ec];                 // 16 MB
__device__ float g_v[(size_t)Bc*Sc*Ec];                 // 16 MB
__device__ float g_o[(size_t)Bc*Tc*Ec];                 // 16 MB  attn output pre-Wo
__device__ float g_p[(size_t)Bc*Hc*Tc*Sc];              // 512 MB probs [B*H, T, S]

// ---------------------------------------------------------------------------
// GEMM: C[M,E] = (A[M,E] @ W[E,E]^T + bias) * scale     (W row-major [out,in])
// 128x128 block tile, BK=16, 256 threads, 8x8 micro-tile, float4 LDS.
// ---------------------------------------------------------------------------
__global__ void __launch_bounds__(256, 2) gemm_proj(
    const float* __restrict__ A, const float* __restrict__ W,
    const float* __restrict__ bias, float* __restrict__ C,
    float scale)
{
    __shared__ float As[16][132];   // [k][m], padded (132%32=4 -> low conflicts, 16B-aligned rows)
    __shared__ float Ws[16][132];   // [k][n]

    const int tid = threadIdx.x;
    const int tx = tid & 15;        // n micro
    const int ty = tid >> 4;        // m micro
    const int lk = tid & 15;        // k lane for loads
    const int lr = tid >> 4;        // row base for loads

    const int bm = blockIdx.y * 128;
    const int bn = blockIdx.x * 128;

    float acc[8][8];
    #pragma unroll
    for (int i = 0; i < 8; i++)
        #pragma unroll
        for (int j = 0; j < 8; j++) acc[i][j] = 0.f;

    for (int k0 = 0; k0 < Ec; k0 += 16) {
        #pragma unroll
        for (int r = 0; r < 8; r++) {
            int row = lr + r * 16;
            As[lk][row] = A[(size_t)(bm + row) * Ec + k0 + lk];
            Ws[lk][row] = W[(size_t)(bn + row) * Ec + k0 + lk];
        }
        __syncthreads();
        #pragma unroll
        for (int kk = 0; kk < 16; kk++) {
            float4 a0 = *(const float4*)&As[kk][ty * 8];
            float4 a1 = *(const float4*)&As[kk][ty * 8 + 4];
            float4 b0 = *(const float4*)&Ws[kk][tx * 8];
            float4 b1 = *(const float4*)&Ws[kk][tx * 8 + 4];
            float a[8] = {a0.x,a0.y,a0.z,a0.w,a1.x,a1.y,a1.z,a1.w};
            float b[8] = {b0.x,b0.y,b0.z,b0.w,b1.x,b1.y,b1.z,b1.w};
            #pragma unroll
            for (int i = 0; i < 8; i++)
                #pragma unroll
                for (int j = 0; j < 8; j++)
                    acc[i][j] += a[i] * b[j];
        }
        __syncthreads();
    }

    #pragma unroll
    for (int i = 0; i < 8; i++) {
        int row = bm + ty * 8 + i;
        #pragma unroll
        for (int j = 0; j < 8; j++) {
            int col = bn + tx * 8 + j;
            C[(size_t)row * Ec + col] = (acc[i][j] + bias[col]) * scale;
        }
    }
}

// ---------------------------------------------------------------------------
// Scores: g_p[bh, t, s] = sum_d q[b,t,h,d]*k[b,s,h,d]  (masked -> 1e-10)
// per (b,h): 2048x2048x64.  128x128 tile, BK=16.
// ---------------------------------------------------------------------------
__global__ void __launch_bounds__(256, 2) score_kernel(
    const unsigned char* __restrict__ attn_mask,   // [T,S] bool
    const unsigned char* __restrict__ kpm)         // [B,S] bool
{
    const int bh = blockIdx.z;
    const int b  = bh >> 4;        // /Hc
    const int h  = bh & 15;
    const int bt = blockIdx.y * 128;
    const int bs = blockIdx.x * 128;

    __shared__ float Qs[16][132];
    __shared__ float Ks[16][132];

    const int tid = threadIdx.x;
    const int tx = tid & 15;
    const int ty = tid >> 4;
    const int lk = tid & 15;
    const int lr = tid >> 4;

    float acc[8][8];
    #pragma unroll
    for (int i = 0; i < 8; i++)
        #pragma unroll
        for (int j = 0; j < 8; j++) acc[i][j] = 0.f;

    for (int k0 = 0; k0 < HDc; k0 += 16) {
        #pragma unroll
        for (int r = 0; r < 8; r++) {
            int row = lr + r * 16;
            Qs[lk][row] = g_q[(((size_t)b * Tc + bt + row) * Hc + h) * HDc + k0 + lk];
            Ks[lk][row] = g_k[(((size_t)b * Sc + bs + row) * Hc + h) * HDc + k0 + lk];
        }
        __syncthreads();
        #pragma unroll
        for (int kk = 0; kk < 16; kk++) {
            float4 a0 = *(const float4*)&Qs[kk][ty * 8];
            float4 a1 = *(const float4*)&Qs[kk][ty * 8 + 4];
            float4 b0 = *(const float4*)&Ks[kk][tx * 8];
            float4 b1 = *(const float4*)&Ks[kk][tx * 8 + 4];
            float a[8] = {a0.x,a0.y,a0.z,a0.w,a1.x,a1.y,a1.z,a1.w};
            float bb[8] = {b0.x,b0.y,b0.z,b0.w,b1.x,b1.y,b1.z,b1.w};
            #pragma unroll
            for (int i = 0; i < 8; i++)
                #pragma unroll
                for (int j = 0; j < 8; j++)
                    acc[i][j] += a[i] * bb[j];
        }
        __syncthreads();
    }

    #pragma unroll
    for (int i = 0; i < 8; i++) {
        int t = bt + ty * 8 + i;
        #pragma unroll
        for (int j = 0; j < 8; j++) {
            int s = bs + tx * 8 + j;
            float v = acc[i][j];
            if (attn_mask[(size_t)t * Sc + s] | kpm[(size_t)b * Sc + s]) v = 1e-10f;
            g_p[((size_t)bh * Tc + t) * Sc + s] = v;
        }
    }
}

// ---------------------------------------------------------------------------
// Softmax over last dim, in place.  One block per row (B*H*T rows), 256 thr.
// ---------------------------------------------------------------------------
__global__ void __launch_bounds__(256) softmax_kernel()
{
    const size_t row = blockIdx.x;
    float* p = g_p + row * Sc;
    const int tid = threadIdx.x;

    float4 v0 = *(const float4*)&p[tid * 8];
    float4 v1 = *(const float4*)&p[tid * 8 + 4];
    float v[8] = {v0.x,v0.y,v0.z,v0.w,v1.x,v1.y,v1.z,v1.w};

    float m = v[0];
    #pragma unroll
    for (int i = 1; i < 8; i++) m = fmaxf(m, v[i]);
    #pragma unroll
    for (int o = 16; o > 0; o >>= 1)
        m = fmaxf(m, __shfl_xor_sync(0xffffffffu, m, o));

    __shared__ float red[8];
    if ((tid & 31) == 0) red[tid >> 5] = m;
    __syncthreads();
    float mm = red[0];
    #pragma unroll
    for (int i = 1; i < 8; i++) mm = fmaxf(mm, red[i]);
    __syncthreads();

    float e[8], s = 0.f;
    #pragma unroll
    for (int i = 0; i < 8; i++) { e[i] = expf(v[i] - mm); s += e[i]; }
    #pragma unroll
    for (int o = 16; o > 0; o >>= 1)
        s += __shfl_xor_sync(0xffffffffu, s, o);
    if ((tid & 31) == 0) red[tid >> 5] = s;
    __syncthreads();
    float tot = 0.f;
    #pragma unroll
    for (int i = 0; i < 8; i++) tot += red[i];
    float inv = 1.0f / tot;

    float4 w0 = make_float4(e[0]*inv, e[1]*inv, e[2]*inv, e[3]*inv);
    float4 w1 = make_float4(e[4]*inv, e[5]*inv, e[6]*inv, e[7]*inv);
    *(float4*)&p[tid * 8]     = w0;
    *(float4*)&p[tid * 8 + 4] = w1;
}

// ---------------------------------------------------------------------------
// attn_max[b,t,s] = max_h probs[b,h,t,s]
// ---------------------------------------------------------------------------
__global__ void __launch_bounds__(256) headmax_kernel(float* __restrict__ out2)
{
    size_t i = (size_t)blockIdx.x * 256 + threadIdx.x;   // over B*T*S
    size_t b = i / ((size_t)Tc * Sc);
    size_t r = i % ((size_t)Tc * Sc);   // t*S + s
    float m = -1e30f;
    #pragma unroll
    for (int h = 0; h < Hc; h++)
        m = fmaxf(m, g_p[((size_t)(b * Hc + h) * Tc) * Sc + r]);
    out2[i] = m;
}

// ---------------------------------------------------------------------------
// PV: g_o[b,t,h,d] = sum_s probs[bh,t,s] * v[b,s,h,d]
// per (b,h): M=2048(t) x N=64(d) x K=2048(s). 128x64 tile, BK=16,
// 256 threads, 8(t)x4(d) micro-tile.
// ---------------------------------------------------------------------------
__global__ void __launch_bounds__(256, 2) pv_kernel()
{
    const int bh = blockIdx.z;
    const int b  = bh >> 4;
    const int h  = bh & 15;
    const int bt = blockIdx.y * 128;

    __shared__ float Ps[16][132];   // [s][t]
    __shared__ float Vs[16][68];    // [s][d]

    const int tid = threadIdx.x;
    const int tx = tid & 15;        // d micro (4)
    const int ty = tid >> 4;        // t micro (8)
    const int lk = tid & 15;
    const int lr = tid >> 4;
    const int vc = tid & 63;        // v load col
    const int vr = tid >> 6;        // v load row base (4 rows/pass)

    float acc[8][4];
    #pragma unroll
    for (int i = 0; i < 8; i++)
        #pragma unroll
        for (int j = 0; j < 4; j++) acc[i][j] = 0.f;

    for (int s0 = 0; s0 < Sc; s0 += 16) {
        #pragma unroll
        for (int r = 0; r < 8; r++) {
            int row = lr + r * 16;
            Ps[lk][row] = g_p[((size_t)bh * Tc + bt + row) * Sc + s0 + lk];
        }
        #pragma unroll
        for (int r = 0; r < 4; r++) {
            int srow = vr + r * 4;
            Vs[srow][vc] = g_v[(((size_t)b * Sc + s0 + srow) * Hc + h) * HDc + vc];
        }
        __syncthreads();
        #pragma unroll
        for (int ss = 0; ss < 16; ss++) {
            float4 a0 = *(const float4*)&Ps[ss][ty * 8];
            float4 a1 = *(const float4*)&Ps[ss][ty * 8 + 4];
            float4 bv = *(const float4*)&Vs[ss][tx * 4];
            float a[8] = {a0.x,a0.y,a0.z,a0.w,a1.x,a1.y,a1.z,a1.w};
            float bb[4] = {bv.x,bv.y,bv.z,bv.w};
            #pragma unroll
            for (int i = 0; i < 8; i++)
                #pragma unroll
                for (int j = 0; j < 4; j++)
                    acc[i][j] += a[i] * bb[j];
        }
        __syncthreads();
    }

    #pragma unroll
    for (int i = 0; i < 8; i++) {
        int t = bt + ty * 8 + i;
        #pragma unroll
        for (int j = 0; j < 4; j++) {
            int d = tx * 4 + j;
            g_o[(((size_t)b * Tc + t) * Hc + h) * HDc + d] = acc[i][j];
        }
    }
}

// ---------------------------------------------------------------------------
extern "C" void kernel_launch(void* const* d_in, const int* in_sizes, int n_in,
                              void* d_out, int out_size)
{
    const float* query = (const float*)d_in[0];
    const float* key   = (const float*)d_in[1];
    const float* value = (const float*)d_in[2];
    const unsigned char* kpm       = (const unsigned char*)d_in[3];
    const unsigned char* attn_mask = (const unsigned char*)d_in[4];
    const float* Wq = (const float*)d_in[5];
    const float* bq = (const float*)d_in[6];
    const float* Wk = (const float*)d_in[7];
    const float* bk = (const float*)d_in[8];
    const float* Wv = (const float*)d_in[9];
    const float* bv = (const float*)d_in[10];
    const float* Wo = (const float*)d_in[11];
    const float* bo = (const float*)d_in[12];

    float* out      = (float*)d_out;                        // [B,T,E]
    float* attn_max = (float*)d_out + (size_t)Bc * Tc * Ec; // [B,T,S]

    // resolve device symbols for kernels that take scratch as args
    float *pq, *pk, *pv_, *po;
    cudaGetSymbolAddress((void**)&pq, g_q);
    cudaGetSymbolAddress((void**)&pk, g_k);
    cudaGetSymbolAddress((void**)&pv_, g_v);
    cudaGetSymbolAddress((void**)&po, g_o);

    dim3 thr(256);
    // Projections
    gemm_proj<<<dim3(Ec / 128, MROWS / 128), thr>>>(query, Wq, bq, pq, QSCALE);
    gemm_proj<<<dim3(Ec / 128, MROWS / 128), thr>>>(key,   Wk, bk, pk, 1.0f);
    gemm_proj<<<dim3(Ec / 128, MROWS / 128), thr>>>(value, Wv, bv, pv_, 1.0f);
    // Scores + mask
    score_kernel<<<dim3(Sc / 128, Tc / 128, Bc * Hc), thr>>>(attn_mask, kpm);
    // Softmax (in place on g_p)
    softmax_kernel<<<dim3(Bc * Hc * Tc), thr>>>();
    // Head-max output
    headmax_kernel<<<dim3((unsigned)(((size_t)Bc * Tc * Sc) / 256)), thr>>>(attn_max);
    // probs @ V
    pv_kernel<<<dim3(1, Tc / 128, Bc * Hc), thr>>>();
    // Output projection
    gemm_proj<<<dim3(Ec / 128, MROWS / 128), thr>>>(po, Wo, bo, out, 1.0f);
}

// round 5
// speedup vs baseline: 2.1948x; 2.1948x over previous
#include <cuda_runtime.h>
#include <cstdint>
#include <math.h>

#define Bc 2
#define Tc 2048
#define Sc 2048
#define Ec 1024
#define Hc 16
#define HDc 64
#define QSCALE 0.125f

// Scratch (__device__ globals; allocation-free)
__device__ float g_q[(size_t)Bc*Hc*Tc*HDc];   // [b,h,t,d]
__device__ float g_k[(size_t)Bc*Hc*Sc*HDc];   // [b,h,s,d]
__device__ float g_vt[(size_t)Bc*Hc*HDc*Sc];  // [b,h,d,s]  (V transposed)
__device__ float g_o[(size_t)Bc*Tc*Ec];       // [b,t,h,d]  attn out pre-Wo
__device__ float g_p[(size_t)Bc*Hc*Tc*Sc];    // [bh,t,s]   probs (512 MB)

__device__ __forceinline__ uint32_t cvt_tf32(float f) {
    uint32_t r; asm("cvt.rna.tf32.f32 %0, %1;" : "=r"(r) : "f"(f)); return r;
}

// mma.sync m16n8k8 tf32 (sm_80+ baseline; drives tensor pipe without tcgen05)
__device__ __forceinline__ void mma_tf32(float c[4], const uint32_t a[4], const uint32_t b[2]) {
    asm volatile(
        "mma.sync.aligned.m16n8k8.row.col.f32.tf32.tf32.f32 "
        "{%0,%1,%2,%3}, {%4,%5,%6,%7}, {%8,%9}, {%0,%1,%2,%3};"
        : "+f"(c[0]), "+f"(c[1]), "+f"(c[2]), "+f"(c[3])
        : "r"(a[0]), "r"(a[1]), "r"(a[2]), "r"(a[3]), "r"(b[0]), "r"(b[1]));
}

// ---------------------------------------------------------------------------
// Tensor-core GEMM (tf32 mma.sync): C[BMxBN] tiles of  C = A[M,K] @ B[N,K]^T
// MODE: 0=Q proj, 1=K proj, 2=V proj (transposed out), 3=O proj, 4=score, 5=PV
// 256 threads / 8 warps.  BN=128 -> warps 2x4 (warp tile 64x32);
// BN=64 -> warps 4x2 (warp tile 32x32).  BK=32 (4 x k8 steps).
// ---------------------------------------------------------------------------
template<int MODE, int BN>
__global__ void __launch_bounds__(256, 2) gemm_mma(
    const float* __restrict__ Abase, const float* __restrict__ Bbase,
    const float* __restrict__ bias, float* __restrict__ Cout,
    int lda, int ldb, int K, float scale,
    const unsigned char* __restrict__ am, const unsigned char* __restrict__ kpm)
{
    constexpr int BM = 128;
    constexpr int WR = (BN == 128) ? 2 : 4;       // warp rows
    constexpr int WC = 8 / WR;                    // warp cols
    constexpr int WM = BM / WR;                   // 64 or 32
    constexpr int WN = BN / WC;                   // 32
    constexpr int MT = WM / 16;                   // 4 or 2
    constexpr int NT = WN / 8;                    // 4

    __shared__ uint32_t As[BM][36];
    __shared__ uint32_t Bs[BN][36];

    const int tid  = threadIdx.x;
    const int wid  = tid >> 5;
    const int lane = tid & 31;
    const int wrow = wid / WC;
    const int wcol = wid % WC;
    const int bm = blockIdx.y * BM;
    const int bn = blockIdx.x * BN;
    const int bh = blockIdx.z;

    const float* A = Abase;
    const float* B = Bbase;
    if (MODE == 4) {
        A = Abase + (size_t)bh * Tc * HDc;
        B = Bbase + (size_t)bh * Sc * HDc;
    } else if (MODE == 5) {
        A = g_p  + (size_t)bh * Tc * Sc;
        B = g_vt + (size_t)bh * HDc * Sc;
    }

    float c[MT][NT][4];
    #pragma unroll
    for (int i = 0; i < MT; i++)
        #pragma unroll
        for (int j = 0; j < NT; j++)
            #pragma unroll
            for (int u = 0; u < 4; u++) c[i][j][u] = 0.f;

    const int lrow = lane >> 2;      // 0..7
    const int lk   = lane & 3;       // 0..3

    for (int k0 = 0; k0 < K; k0 += 32) {
        // Load A tile (BM x 32)
        #pragma unroll
        for (int i = 0; i < BM * 32 / 1024; i++) {
            int flat = tid + i * 256;
            int row = flat >> 3, c4 = (flat & 7) * 4;
            float4 v = *(const float4*)(A + (size_t)(bm + row) * lda + k0 + c4);
            *(uint4*)&As[row][c4] = make_uint4(cvt_tf32(v.x), cvt_tf32(v.y),
                                               cvt_tf32(v.z), cvt_tf32(v.w));
        }
        // Load B tile (BN x 32)
        #pragma unroll
        for (int i = 0; i < BN * 32 / 1024; i++) {
            int flat = tid + i * 256;
            int row = flat >> 3, c4 = (flat & 7) * 4;
            float4 v = *(const float4*)(B + (size_t)(bn + row) * ldb + k0 + c4);
            *(uint4*)&Bs[row][c4] = make_uint4(cvt_tf32(v.x), cvt_tf32(v.y),
                                               cvt_tf32(v.z), cvt_tf32(v.w));
        }
        __syncthreads();

        #pragma unroll
        for (int k8 = 0; k8 < 4; k8++) {
            uint32_t af[MT][4], bf[NT][2];
            #pragma unroll
            for (int mt = 0; mt < MT; mt++) {
                int r0 = wrow * WM + mt * 16 + lrow;
                af[mt][0] = As[r0    ][k8 * 8 + lk];
                af[mt][1] = As[r0 + 8][k8 * 8 + lk];
                af[mt][2] = As[r0    ][k8 * 8 + lk + 4];
                af[mt][3] = As[r0 + 8][k8 * 8 + lk + 4];
            }
            #pragma unroll
            for (int nt = 0; nt < NT; nt++) {
                int n0 = wcol * WN + nt * 8 + lrow;
                bf[nt][0] = Bs[n0][k8 * 8 + lk];
                bf[nt][1] = Bs[n0][k8 * 8 + lk + 4];
            }
            #pragma unroll
            for (int mt = 0; mt < MT; mt++)
                #pragma unroll
                for (int nt = 0; nt < NT; nt++)
                    mma_tf32(c[mt][nt], af[mt], bf[nt]);
        }
        __syncthreads();
    }

    // Epilogue: each (mt,nt) frag covers rows {r, r+8}, cols {col, col+1}
    #pragma unroll
    for (int mt = 0; mt < MT; mt++) {
        #pragma unroll
        for (int nt = 0; nt < NT; nt++) {
            #pragma unroll
            for (int half = 0; half < 2; half++) {
                int row = bm + wrow * WM + mt * 16 + lrow + half * 8;
                int col = bn + wcol * WN + nt * 8 + (lane & 3) * 2;
                float v0 = c[mt][nt][half * 2];
                float v1 = c[mt][nt][half * 2 + 1];

                if (MODE == 0 || MODE == 1) {
                    int b = row >> 11, t = row & 2047;
                    int h = col >> 6, d = col & 63;
                    float* dst = (MODE == 0 ? g_q : g_k)
                               + (((size_t)(b * Hc + h)) * Tc + t) * HDc + d;
                    *(float2*)dst = make_float2((v0 + bias[col]) * scale,
                                                (v1 + bias[col + 1]) * scale);
                } else if (MODE == 2) {
                    int b = row >> 11, s = row & 2047;
                    int h = col >> 6, d = col & 63;
                    size_t base = ((size_t)(b * Hc + h)) * HDc;
                    g_vt[(base + d) * Sc + s]     = v0 + bias[col];
                    g_vt[(base + d + 1) * Sc + s] = v1 + bias[col + 1];
                } else if (MODE == 3) {
                    *(float2*)&Cout[(size_t)row * Ec + col] =
                        make_float2(v0 + bias[col], v1 + bias[col + 1]);
                } else if (MODE == 4) {
                    int b = bh >> 4;
                    int t = row, s = col;
                    if (am[(size_t)t * Sc + s] | kpm[(size_t)b * Sc + s]) v0 = 1e-10f;
                    if (am[(size_t)t * Sc + s + 1] | kpm[(size_t)b * Sc + s + 1]) v1 = 1e-10f;
                    *(float2*)&g_p[((size_t)bh * Tc + t) * Sc + s] = make_float2(v0, v1);
                } else { // MODE 5: PV -> g_o[b,t,h,d]
                    int b = bh >> 4, h = bh & 15;
                    int t = row, d = col;
                    *(float2*)&g_o[(((size_t)b * Tc + t) * Hc + h) * HDc + d] =
                        make_float2(v0, v1);
                }
            }
        }
    }
}

// ---------------------------------------------------------------------------
// Softmax over last dim of g_p, in place.  One block per row, 256 threads.
// ---------------------------------------------------------------------------
__global__ void __launch_bounds__(256) softmax_kernel()
{
    const size_t row = blockIdx.x;
    float* p = g_p + row * Sc;
    const int tid = threadIdx.x;

    float4 v0 = *(const float4*)&p[tid * 8];
    float4 v1 = *(const float4*)&p[tid * 8 + 4];
    float v[8] = {v0.x, v0.y, v0.z, v0.w, v1.x, v1.y, v1.z, v1.w};

    float m = v[0];
    #pragma unroll
    for (int i = 1; i < 8; i++) m = fmaxf(m, v[i]);
    #pragma unroll
    for (int o = 16; o > 0; o >>= 1) m = fmaxf(m, __shfl_xor_sync(0xffffffffu, m, o));

    __shared__ float red[8];
    if ((tid & 31) == 0) red[tid >> 5] = m;
    __syncthreads();
    float mm = red[0];
    #pragma unroll
    for (int i = 1; i < 8; i++) mm = fmaxf(mm, red[i]);
    __syncthreads();

    float e[8], s = 0.f;
    #pragma unroll
    for (int i = 0; i < 8; i++) { e[i] = expf(v[i] - mm); s += e[i]; }
    #pragma unroll
    for (int o = 16; o > 0; o >>= 1) s += __shfl_xor_sync(0xffffffffu, s, o);
    if ((tid & 31) == 0) red[tid >> 5] = s;
    __syncthreads();
    float tot = 0.f;
    #pragma unroll
    for (int i = 0; i < 8; i++) tot += red[i];
    float inv = 1.0f / tot;

    *(float4*)&p[tid * 8]     = make_float4(e[0]*inv, e[1]*inv, e[2]*inv, e[3]*inv);
    *(float4*)&p[tid * 8 + 4] = make_float4(e[4]*inv, e[5]*inv, e[6]*inv, e[7]*inv);
}

// ---------------------------------------------------------------------------
// attn_max[b,t,s] = max_h probs[b,h,t,s]
// ---------------------------------------------------------------------------
__global__ void __launch_bounds__(256) headmax_kernel(float* __restrict__ out2)
{
    size_t i = (size_t)blockIdx.x * 256 + threadIdx.x;
    size_t b = i / ((size_t)Tc * Sc);
    size_t r = i % ((size_t)Tc * Sc);
    float m = -1e30f;
    #pragma unroll
    for (int h = 0; h < Hc; h++)
        m = fmaxf(m, g_p[((size_t)(b * Hc + h) * Tc) * Sc + r]);
    out2[i] = m;
}

// ---------------------------------------------------------------------------
extern "C" void kernel_launch(void* const* d_in, const int* in_sizes, int n_in,
                              void* d_out, int out_size)
{
    const float* query = (const float*)d_in[0];
    const float* key   = (const float*)d_in[1];
    const float* value = (const float*)d_in[2];
    const unsigned char* kpm = (const unsigned char*)d_in[3];
    const unsigned char* am  = (const unsigned char*)d_in[4];
    const float* Wq = (const float*)d_in[5];
    const float* bq = (const float*)d_in[6];
    const float* Wk = (const float*)d_in[7];
    const float* bk = (const float*)d_in[8];
    const float* Wv = (const float*)d_in[9];
    const float* bv = (const float*)d_in[10];
    const float* Wo = (const float*)d_in[11];
    const float* bo = (const float*)d_in[12];

    float* out      = (float*)d_out;
    float* attn_max = (float*)d_out + (size_t)Bc * Tc * Ec;

    float *pq, *pk, *po;
    cudaGetSymbolAddress((void**)&pq, g_q);
    cudaGetSymbolAddress((void**)&pk, g_k);
    cudaGetSymbolAddress((void**)&po, g_o);

    dim3 thr(256);
    dim3 gproj(Ec / 128, (Bc * Tc) / 128, 1);   // (8, 32)

    // Projections (tf32 mma.sync)
    gemm_mma<0, 128><<<gproj, thr>>>(query, Wq, bq, nullptr, Ec, Ec, Ec, QSCALE, nullptr, nullptr);
    gemm_mma<1, 128><<<gproj, thr>>>(key,   Wk, bk, nullptr, Ec, Ec, Ec, 1.0f,   nullptr, nullptr);
    gemm_mma<2, 128><<<gproj, thr>>>(value, Wv, bv, nullptr, Ec, Ec, Ec, 1.0f,   nullptr, nullptr);

    // Scores (per-head batched, masked raw scores into g_p)
    gemm_mma<4, 128><<<dim3(Sc / 128, Tc / 128, Bc * Hc), thr>>>(
        pq, pk, nullptr, nullptr, HDc, HDc, HDc, 1.0f, am, kpm);

    // Softmax in place, then head-max output
    softmax_kernel<<<dim3(Bc * Hc * Tc), thr>>>();
    headmax_kernel<<<dim3((unsigned)(((size_t)Bc * Tc * Sc) / 256)), thr>>>(attn_max);

    // P @ V
    gemm_mma<5, 64><<<dim3(1, Tc / 128, Bc * Hc), thr>>>(
        nullptr, nullptr, nullptr, nullptr, Sc, Sc, Sc, 1.0f, nullptr, nullptr);

    // Output projection
    gemm_mma<3, 128><<<gproj, thr>>>(po, Wo, bo, out, Ec, Ec, Ec, 1.0f, nullptr, nullptr);
}

// round 6
// speedup vs baseline: 2.4173x; 1.1014x over previous
#include <cuda_runtime.h>
#include <cstdint>
#include <math.h>

#define Bc 2
#define Tc 2048
#define Sc 2048
#define Ec 1024
#define Hc 16
#define HDc 64
#define QSCALE 0.125f

// Scratch (__device__ globals; allocation-free)
__device__ float g_q[(size_t)Bc*Hc*Tc*HDc];   // [b,h,t,d]
__device__ float g_k[(size_t)Bc*Hc*Sc*HDc];   // [b,h,s,d]
__device__ float g_v[(size_t)Bc*Hc*Sc*HDc];   // [b,h,s,d]
__device__ float g_o[(size_t)Bc*Tc*Ec];       // [b,t,h,d]  attn out pre-Wo
__device__ float g_p[(size_t)Bc*Hc*Tc*Sc];    // [bh,t,s]   raw masked scores (512 MB)
__device__ int   g_m[Bc*Hc*Tc];               // ordered-int row max
__device__ float g_c[Bc*Hc*Tc];               // m + log(sum)

__device__ __forceinline__ uint32_t cvt_tf32(float f) {
    uint32_t r; asm("cvt.rna.tf32.f32 %0, %1;" : "=r"(r) : "f"(f)); return r;
}
__device__ __forceinline__ uint32_t smem_u32(const void* p) {
    uint32_t a;
    asm("{ .reg .u64 t; cvta.to.shared.u64 t, %1; cvt.u32.u64 %0, t; }" : "=r"(a) : "l"(p));
    return a;
}
__device__ __forceinline__ void mma_tf32(float c[4], const uint32_t a[4], const uint32_t b[2]) {
    asm volatile(
        "mma.sync.aligned.m16n8k8.row.col.f32.tf32.tf32.f32 "
        "{%0,%1,%2,%3}, {%4,%5,%6,%7}, {%8,%9}, {%0,%1,%2,%3};"
        : "+f"(c[0]), "+f"(c[1]), "+f"(c[2]), "+f"(c[3])
        : "r"(a[0]), "r"(a[1]), "r"(a[2]), "r"(a[3]), "r"(b[0]), "r"(b[1]));
}
__device__ __forceinline__ void ldsm4(uint32_t r[4], uint32_t addr) {
    asm volatile("ldmatrix.sync.aligned.m8n8.x4.shared.b16 {%0,%1,%2,%3}, [%4];"
        : "=r"(r[0]), "=r"(r[1]), "=r"(r[2]), "=r"(r[3]) : "r"(addr));
}
// ordered-int float atomic max (monotone encode)
__device__ __forceinline__ void atomicMaxF(int* addr, float v) {
    int iv = __float_as_int(v);
    int ord = iv >= 0 ? iv : iv ^ 0x7FFFFFFF;
    atomicMax(addr, ord);
}
__device__ __forceinline__ float decodeOrd(int o) {
    return __int_as_float(o >= 0 ? o : o ^ 0x7FFFFFFF);
}

__global__ void initm_kernel() {
    int i = blockIdx.x * 256 + threadIdx.x;
    if (i < Bc * Hc * Tc) g_m[i] = 0x807FFFFF;   // ordered encode of -inf
}

// ---------------------------------------------------------------------------
// Tensor-core GEMM (tf32 mma.sync + ldmatrix):  C = A[M,K] @ B[N,K]^T
// MODE 0 = projection -> [b,h,t,d]*scale ; 3 = flat out ; 4 = score (+rowmax)
// 256 thr / 8 warps; BM=128, BN=128, BK=32; warps 2x4 (warp tile 64x32).
// ---------------------------------------------------------------------------
template<int MODE>
__global__ void __launch_bounds__(256, 2) gemm_mma(
    const float* __restrict__ Abase, const float* __restrict__ Bbase,
    const float* __restrict__ bias, float* __restrict__ Cout,
    int lda, int ldb, int K, float scale,
    const unsigned char* __restrict__ am, const unsigned char* __restrict__ kpm)
{
    constexpr int BM = 128, BN = 128;
    constexpr int WM = 64, WN = 32;   // 2x4 warp grid
    constexpr int MT = 4, NT = 4;

    __shared__ uint32_t As[BM][36];
    __shared__ uint32_t Bs[BN][36];

    const int tid  = threadIdx.x;
    const int wid  = tid >> 5;
    const int lane = tid & 31;
    const int wrow = wid >> 2;        // 0..1
    const int wcol = wid & 3;         // 0..3
    const int bm = blockIdx.y * BM;
    const int bn = blockIdx.x * BN;
    const int bh = blockIdx.z;

    const float* A = Abase;
    const float* B = Bbase;
    if (MODE == 4) {
        A = Abase + (size_t)bh * Tc * HDc;
        B = Bbase + (size_t)bh * Sc * HDc;
    }

    float c[MT][NT][4];
    #pragma unroll
    for (int i = 0; i < MT; i++)
        #pragma unroll
        for (int j = 0; j < NT; j++)
            #pragma unroll
            for (int u = 0; u < 4; u++) c[i][j][u] = 0.f;

    // ldmatrix per-thread address components
    const int aRow = wrow * WM + (lane & 7) + ((lane >> 3) & 1) * 8;
    const int aCol = (lane >> 4) * 4;
    const int bRow = wcol * WN + ((lane >> 4) * 8) + (lane & 7);
    const int bCol = ((lane >> 3) & 1) * 4;
    const uint32_t sA = smem_u32(&As[0][0]);
    const uint32_t sB = smem_u32(&Bs[0][0]);

    // register-buffered gmem prefetch
    float4 ra[4], rb[4];
    #pragma unroll
    for (int i = 0; i < 4; i++) {
        int flat = tid + i * 256;
        int row = flat >> 3, c4 = (flat & 7) * 4;
        ra[i] = *(const float4*)(A + (size_t)(bm + row) * lda + c4);
        rb[i] = *(const float4*)(B + (size_t)(bn + row) * ldb + c4);
    }

    for (int k0 = 0; k0 < K; k0 += 32) {
        #pragma unroll
        for (int i = 0; i < 4; i++) {
            int flat = tid + i * 256;
            int row = flat >> 3, c4 = (flat & 7) * 4;
            *(uint4*)&As[row][c4] = make_uint4(cvt_tf32(ra[i].x), cvt_tf32(ra[i].y),
                                               cvt_tf32(ra[i].z), cvt_tf32(ra[i].w));
            *(uint4*)&Bs[row][c4] = make_uint4(cvt_tf32(rb[i].x), cvt_tf32(rb[i].y),
                                               cvt_tf32(rb[i].z), cvt_tf32(rb[i].w));
        }
        __syncthreads();
        if (k0 + 32 < K) {
            #pragma unroll
            for (int i = 0; i < 4; i++) {
                int flat = tid + i * 256;
                int row = flat >> 3, c4 = (flat & 7) * 4;
                ra[i] = *(const float4*)(A + (size_t)(bm + row) * lda + k0 + 32 + c4);
                rb[i] = *(const float4*)(B + (size_t)(bn + row) * ldb + k0 + 32 + c4);
            }
        }
        #pragma unroll
        for (int k8 = 0; k8 < 4; k8++) {
            uint32_t af[MT][4], bf[NT][2];
            #pragma unroll
            for (int mt = 0; mt < MT; mt++)
                ldsm4(af[mt], sA + (uint32_t)(((aRow + mt * 16) * 36 + k8 * 8 + aCol) * 4));
            #pragma unroll
            for (int np = 0; np < NT / 2; np++) {
                uint32_t t4[4];
                ldsm4(t4, sB + (uint32_t)(((bRow + np * 16) * 36 + k8 * 8 + bCol) * 4));
                bf[2*np][0] = t4[0]; bf[2*np][1] = t4[1];
                bf[2*np+1][0] = t4[2]; bf[2*np+1][1] = t4[3];
            }
            #pragma unroll
            for (int mt = 0; mt < MT; mt++)
                #pragma unroll
                for (int nt = 0; nt < NT; nt++)
                    mma_tf32(c[mt][nt], af[mt], bf[nt]);
        }
        __syncthreads();
    }

    const int lrow = lane >> 2;
    const int lk   = lane & 3;

    #pragma unroll
    for (int mt = 0; mt < MT; mt++) {
        #pragma unroll
        for (int half = 0; half < 2; half++) {
            int row = bm + wrow * WM + mt * 16 + lrow + half * 8;
            float rmax = -1e30f;
            #pragma unroll
            for (int nt = 0; nt < NT; nt++) {
                int col = bn + wcol * WN + nt * 8 + lk * 2;
                float v0 = c[mt][nt][half * 2];
                float v1 = c[mt][nt][half * 2 + 1];

                if (MODE == 0) {
                    int b = row >> 11, t = row & 2047;
                    int h = col >> 6, d = col & 63;
                    *(float2*)&Cout[(((size_t)(b * Hc + h)) * Tc + t) * HDc + d] =
                        make_float2((v0 + bias[col]) * scale, (v1 + bias[col + 1]) * scale);
                } else if (MODE == 3) {
                    *(float2*)&Cout[(size_t)row * Ec + col] =
                        make_float2(v0 + bias[col], v1 + bias[col + 1]);
                } else { // MODE 4: masked raw scores + row-max atomics
                    int b = bh >> 4;
                    if (am[(size_t)row * Sc + col] | kpm[(size_t)b * Sc + col]) v0 = 1e-10f;
                    if (am[(size_t)row * Sc + col + 1] | kpm[(size_t)b * Sc + col + 1]) v1 = 1e-10f;
                    *(float2*)&g_p[((size_t)bh * Tc + row) * Sc + col] = make_float2(v0, v1);
                    rmax = fmaxf(rmax, fmaxf(v0, v1));
                }
            }
            if (MODE == 4) {
                rmax = fmaxf(rmax, __shfl_xor_sync(0xffffffffu, rmax, 1));
                rmax = fmaxf(rmax, __shfl_xor_sync(0xffffffffu, rmax, 2));
                if (lk == 0) atomicMaxF(&g_m[(size_t)bh * Tc + row], rmax);
            }
        }
    }
}

// ---------------------------------------------------------------------------
// pv_prob: per (bh, t-tile 128).  p = exp(score - m); rowsum; O = (p @ V)/sum;
// writes g_o and c = m + log(sum).  8 warps, each owns 16 t-rows, all 64 d.
// ---------------------------------------------------------------------------
__global__ void __launch_bounds__(256) pv_prob()
{
    extern __shared__ uint32_t dsm[];
    uint32_t* Asm = dsm;                 // [128][132] raw fp32 scores
    uint32_t* Vsm = dsm + 128 * 132;     // [128][72]  tf32 V (rows=s, cols=d)

    const int tid  = threadIdx.x;
    const int wid  = tid >> 5;
    const int lane = tid & 31;
    const int lrow = lane >> 2;
    const int lk   = lane & 3;
    const int bh = blockIdx.y;
    const int b = bh >> 4, h = bh & 15;
    const int tbase = blockIdx.x * 128;
    const int wt = wid * 16;

    const float* P = g_p + ((size_t)bh * Tc + tbase) * Sc;
    const float* V = g_v + (size_t)bh * Sc * HDc;

    // per-warp row stats
    const int r_lo = wt + lrow, r_hi = wt + lrow + 8;
    const float m_lo = decodeOrd(g_m[(size_t)bh * Tc + tbase + r_lo]);
    const float m_hi = decodeOrd(g_m[(size_t)bh * Tc + tbase + r_hi]);
    float sum_lo = 0.f, sum_hi = 0.f;

    float acc[8][4];
    #pragma unroll
    for (int j = 0; j < 8; j++)
        #pragma unroll
        for (int u = 0; u < 4; u++) acc[j][u] = 0.f;

    const int aRow = wt + (lane & 7) + ((lane >> 3) & 1) * 8;
    const int aCol = (lane >> 4) * 4;
    const uint32_t sA = smem_u32(Asm);

    for (int s0 = 0; s0 < Sc; s0 += 128) {
        // stage scores (raw fp32) and V (tf32) into smem
        #pragma unroll
        for (int i = 0; i < 16; i++) {
            int flat = tid + i * 256;
            int row = flat >> 5, c4 = (flat & 31) * 4;
            *(float4*)&Asm[row * 132 + c4] =
                *(const float4*)(P + (size_t)row * Sc + s0 + c4);
        }
        #pragma unroll
        for (int i = 0; i < 8; i++) {
            int flat = tid + i * 256;
            int row = flat >> 4, c4 = (flat & 15) * 4;
            float4 v = *(const float4*)(V + (size_t)(s0 + row) * HDc + c4);
            *(uint4*)&Vsm[row * 72 + c4] = make_uint4(cvt_tf32(v.x), cvt_tf32(v.y),
                                                      cvt_tf32(v.z), cvt_tf32(v.w));
        }
        __syncthreads();

        #pragma unroll
        for (int k8 = 0; k8 < 16; k8++) {
            uint32_t a[4];
            ldsm4(a, sA + (uint32_t)((aRow * 132 + k8 * 8 + aCol) * 4));
            float p0 = expf(__uint_as_float(a[0]) - m_lo);
            float p1 = expf(__uint_as_float(a[1]) - m_hi);
            float p2 = expf(__uint_as_float(a[2]) - m_lo);
            float p3 = expf(__uint_as_float(a[3]) - m_hi);
            sum_lo += p0 + p2;
            sum_hi += p1 + p3;
            uint32_t pa[4] = {cvt_tf32(p0), cvt_tf32(p1), cvt_tf32(p2), cvt_tf32(p3)};
            #pragma unroll
            for (int nt = 0; nt < 8; nt++) {
                uint32_t bfr[2];
                bfr[0] = Vsm[(k8 * 8 + lk) * 72 + nt * 8 + lrow];
                bfr[1] = Vsm[(k8 * 8 + lk + 4) * 72 + nt * 8 + lrow];
                mma_tf32(acc[nt], pa, bfr);
            }
        }
        __syncthreads();
    }

    // reduce row sums across the 4 lanes sharing lrow
    sum_lo += __shfl_xor_sync(0xffffffffu, sum_lo, 1);
    sum_lo += __shfl_xor_sync(0xffffffffu, sum_lo, 2);
    sum_hi += __shfl_xor_sync(0xffffffffu, sum_hi, 1);
    sum_hi += __shfl_xor_sync(0xffffffffu, sum_hi, 2);
    const float inv_lo = 1.0f / sum_lo;
    const float inv_hi = 1.0f / sum_hi;

    const int t_lo = tbase + r_lo, t_hi = tbase + r_hi;
    #pragma unroll
    for (int nt = 0; nt < 8; nt++) {
        int d = nt * 8 + lk * 2;
        *(float2*)&g_o[(((size_t)b * Tc + t_lo) * Hc + h) * HDc + d] =
            make_float2(acc[nt][0] * inv_lo, acc[nt][1] * inv_lo);
        *(float2*)&g_o[(((size_t)b * Tc + t_hi) * Hc + h) * HDc + d] =
            make_float2(acc[nt][2] * inv_hi, acc[nt][3] * inv_hi);
    }
    if (lk == 0) {
        g_c[(size_t)bh * Tc + t_lo] = m_lo + logf(sum_lo);
        g_c[(size_t)bh * Tc + t_hi] = m_hi + logf(sum_hi);
    }
}

// ---------------------------------------------------------------------------
// headmax: attn_max[b,t,s] = exp(max_h (score[b,h,t,s] - c[b,h,t]))
// ---------------------------------------------------------------------------
__global__ void __launch_bounds__(256) headmax_kernel(float* __restrict__ out2)
{
    size_t i4 = (size_t)blockIdx.x * 256 + threadIdx.x;  // over B*T*S/4
    size_t sq = i4 % (Sc / 4);
    size_t bt = i4 / (Sc / 4);      // b*T + t
    size_t b = bt >> 11, t = bt & 2047;
    size_t s = sq * 4;

    float4 best = make_float4(-1e30f, -1e30f, -1e30f, -1e30f);
    #pragma unroll
    for (int h = 0; h < Hc; h++) {
        size_t bh = b * Hc + h;
        float ch = g_c[bh * Tc + t];
        float4 sc = *(const float4*)&g_p[(bh * Tc + t) * Sc + s];
        best.x = fmaxf(best.x, sc.x - ch);
        best.y = fmaxf(best.y, sc.y - ch);
        best.z = fmaxf(best.z, sc.z - ch);
        best.w = fmaxf(best.w, sc.w - ch);
    }
    *(float4*)&out2[bt * Sc + s] =
        make_float4(expf(best.x), expf(best.y), expf(best.z), expf(best.w));
}

// ---------------------------------------------------------------------------
extern "C" void kernel_launch(void* const* d_in, const int* in_sizes, int n_in,
                              void* d_out, int out_size)
{
    const float* query = (const float*)d_in[0];
    const float* key   = (const float*)d_in[1];
    const float* value = (const float*)d_in[2];
    const unsigned char* kpm = (const unsigned char*)d_in[3];
    const unsigned char* am  = (const unsigned char*)d_in[4];
    const float* Wq = (const float*)d_in[5];
    const float* bq = (const float*)d_in[6];
    const float* Wk = (const float*)d_in[7];
    const float* bk = (const float*)d_in[8];
    const float* Wv = (const float*)d_in[9];
    const float* bv = (const float*)d_in[10];
    const float* Wo = (const float*)d_in[11];
    const float* bo = (const float*)d_in[12];

    float* out      = (float*)d_out;
    float* attn_max = (float*)d_out + (size_t)Bc * Tc * Ec;

    float *pq, *pk, *pv_, *po;
    cudaGetSymbolAddress((void**)&pq, g_q);
    cudaGetSymbolAddress((void**)&pk, g_k);
    cudaGetSymbolAddress((void**)&pv_, g_v);
    cudaGetSymbolAddress((void**)&po, g_o);

    const int PV_SMEM = (128 * 132 + 128 * 72) * 4;   // 104448
    static int attr_done = 0;
    cudaFuncSetAttribute(pv_prob, cudaFuncAttributeMaxDynamicSharedMemorySize, PV_SMEM);
    (void)attr_done;

    dim3 thr(256);
    dim3 gproj(Ec / 128, (Bc * Tc) / 128, 1);   // (8, 32)

    // init row-max
    initm_kernel<<<dim3((Bc * Hc * Tc + 255) / 256), thr>>>();

    // Projections (Q/K/V -> [b,h,t,d])
    gemm_mma<0><<<gproj, thr>>>(query, Wq, bq, pq,  Ec, Ec, Ec, QSCALE, nullptr, nullptr);
    gemm_mma<0><<<gproj, thr>>>(key,   Wk, bk, pk,  Ec, Ec, Ec, 1.0f,   nullptr, nullptr);
    gemm_mma<0><<<gproj, thr>>>(value, Wv, bv, pv_, Ec, Ec, Ec, 1.0f,   nullptr, nullptr);

    // Scores: masked raw scores into g_p + atomic row max into g_m
    gemm_mma<4><<<dim3(Sc / 128, Tc / 128, Bc * Hc), thr>>>(
        pq, pk, nullptr, nullptr, HDc, HDc, HDc, 1.0f, am, kpm);

    // Fused softmax + P@V:  writes g_o and c = m + log(sum)
    pv_prob<<<dim3(Tc / 128, Bc * Hc), thr, PV_SMEM>>>();

    // attn_max output
    headmax_kernel<<<dim3((unsigned)(((size_t)Bc * Tc * Sc / 4) / 256)), thr>>>(attn_max);

    // Output projection
    gemm_mma<3><<<gproj, thr>>>(po, Wo, bo, out, Ec, Ec, Ec, 1.0f, nullptr, nullptr);
}

// round 8
// speedup vs baseline: 2.6210x; 1.0843x over previous
#include <cuda_runtime.h>
#include <cstdint>
#include <math.h>

#define Bc 2
#define Tc 2048
#define Sc 2048
#define Ec 1024
#define Hc 16
#define HDc 64
#define QSCALE 0.125f

// Scratch (__device__ globals; allocation-free)
__device__ float g_q[(size_t)Bc*Hc*Tc*HDc];   // [b,h,t,d]
__device__ float g_k[(size_t)Bc*Hc*Sc*HDc];   // [b,h,s,d]
__device__ float g_v[(size_t)Bc*Hc*Sc*HDc];   // [b,h,s,d]
__device__ float g_o[(size_t)Bc*Tc*Ec];       // [b,t,h,d]  attn out pre-Wo
__device__ float g_p[(size_t)Bc*Hc*Tc*Sc];    // [bh,t,s]   raw masked scores (512 MB)
__device__ int   g_m[Bc*Hc*Tc];               // ordered-int row max
__device__ float g_c[Bc*Hc*Tc];               // m + log(sum)

__device__ __forceinline__ uint32_t cvt_tf32(float f) {
    uint32_t r; asm("cvt.rna.tf32.f32 %0, %1;" : "=r"(r) : "f"(f)); return r;
}
__device__ __forceinline__ uint32_t smem_u32(const void* p) {
    uint32_t a;
    asm("{ .reg .u64 t; cvta.to.shared.u64 t, %1; cvt.u32.u64 %0, t; }" : "=r"(a) : "l"(p));
    return a;
}
__device__ __forceinline__ void mma_tf32(float c[4], const uint32_t a[4], const uint32_t b[2]) {
    asm volatile(
        "mma.sync.aligned.m16n8k8.row.col.f32.tf32.tf32.f32 "
        "{%0,%1,%2,%3}, {%4,%5,%6,%7}, {%8,%9}, {%0,%1,%2,%3};"
        : "+f"(c[0]), "+f"(c[1]), "+f"(c[2]), "+f"(c[3])
        : "r"(a[0]), "r"(a[1]), "r"(a[2]), "r"(a[3]), "r"(b[0]), "r"(b[1]));
}
__device__ __forceinline__ void ldsm4(uint32_t r[4], uint32_t addr) {
    asm volatile("ldmatrix.sync.aligned.m8n8.x4.shared.b16 {%0,%1,%2,%3}, [%4];"
        : "=r"(r[0]), "=r"(r[1]), "=r"(r[2]), "=r"(r[3]) : "r"(addr));
}
__device__ __forceinline__ void atomicMaxF(int* addr, float v) {
    int iv = __float_as_int(v);
    int ord = iv >= 0 ? iv : iv ^ 0x7FFFFFFF;
    atomicMax(addr, ord);
}
__device__ __forceinline__ float decodeOrd(int o) {
    return __int_as_float(o >= 0 ? o : o ^ 0x7FFFFFFF);
}

__global__ void initm_kernel() {
    int i = blockIdx.x * 256 + threadIdx.x;
    if (i < Bc * Hc * Tc) g_m[i] = 0x807FFFFF;   // ordered encode of -inf
}

// ---------------------------------------------------------------------------
// Double-buffered tf32 GEMM:  C = A[M,1024] @ W[1024,1024]^T (+bias)
// MODE 0: batched QKV projection (blockIdx.z selects q/k/v) -> g_q/g_k/g_v
// MODE 3: output projection (flat [row, col] out)
// 256 thr / 8 warps; BM=BN=128, BK=32; warps 2x4; one __syncthreads per K-iter.
// ---------------------------------------------------------------------------
template<int MODE>
__global__ void __launch_bounds__(256, 2) gemm_db(
    const float* __restrict__ A0, const float* __restrict__ A1, const float* __restrict__ A2,
    const float* __restrict__ W0, const float* __restrict__ W1, const float* __restrict__ W2,
    const float* __restrict__ bias0, const float* __restrict__ bias1, const float* __restrict__ bias2,
    float* __restrict__ Cout)
{
    extern __shared__ uint32_t ds[];
    // buffers: A0s[128][36], B0s[128][36], A1s, B1s
    uint32_t* const Abuf[2] = { ds,         ds + 9216 };
    uint32_t* const Bbuf[2] = { ds + 4608,  ds + 13824 };

    const int tid  = threadIdx.x;
    const int wid  = tid >> 5;
    const int lane = tid & 31;
    const int wrow = wid >> 2;        // 0..1
    const int wcol = wid & 3;         // 0..3
    const int bm = blockIdx.y * 128;
    const int bn = blockIdx.x * 128;
    const int z  = blockIdx.z;

    const float* A; const float* W; const float* bias; float scale; float* dst;
    if (MODE == 0) {
        A    = (z == 0) ? A0 : (z == 1) ? A1 : A2;
        W    = (z == 0) ? W0 : (z == 1) ? W1 : W2;
        bias = (z == 0) ? bias0 : (z == 1) ? bias1 : bias2;
        scale = (z == 0) ? QSCALE : 1.0f;
        dst  = (z == 0) ? g_q : (z == 1) ? g_k : g_v;
    } else {
        A = A0; W = W0; bias = bias0; scale = 1.0f; dst = Cout;
    }

    float c[4][4][4];
    #pragma unroll
    for (int i = 0; i < 4; i++)
        #pragma unroll
        for (int j = 0; j < 4; j++)
            #pragma unroll
            for (int u = 0; u < 4; u++) c[i][j][u] = 0.f;

    const int aRow = wrow * 64 + (lane & 7) + ((lane >> 3) & 1) * 8;
    const int aCol = (lane >> 4) * 4;
    const int bRow = wcol * 32 + ((lane >> 4) * 8) + (lane & 7);
    const int bCol = ((lane >> 3) & 1) * 4;
    const uint32_t sA[2] = { smem_u32(Abuf[0]), smem_u32(Abuf[1]) };
    const uint32_t sB[2] = { smem_u32(Bbuf[0]), smem_u32(Bbuf[1]) };

    const int lrw = tid >> 3;          // load row (0..31 step over 128 via *4)
    const int lc4 = (tid & 7) * 4;     // load col

    // preload tile 0 into buf0
    float4 ra[4], rb[4];
    #pragma unroll
    for (int i = 0; i < 4; i++) {
        int row = lrw + i * 32;
        ra[i] = *(const float4*)(A + (size_t)(bm + row) * Ec + lc4);
        rb[i] = *(const float4*)(W + (size_t)(bn + row) * Ec + lc4);
    }
    #pragma unroll
    for (int i = 0; i < 4; i++) {
        int row = lrw + i * 32;
        *(uint4*)&Abuf[0][row * 36 + lc4] = make_uint4(cvt_tf32(ra[i].x), cvt_tf32(ra[i].y),
                                                       cvt_tf32(ra[i].z), cvt_tf32(ra[i].w));
        *(uint4*)&Bbuf[0][row * 36 + lc4] = make_uint4(cvt_tf32(rb[i].x), cvt_tf32(rb[i].y),
                                                       cvt_tf32(rb[i].z), cvt_tf32(rb[i].w));
    }
    __syncthreads();

    for (int ks = 0; ks < 32; ks++) {
        const int cur = ks & 1;
        if (ks < 31) {
            #pragma unroll
            for (int i = 0; i < 4; i++) {
                int row = lrw + i * 32;
                ra[i] = *(const float4*)(A + (size_t)(bm + row) * Ec + (ks + 1) * 32 + lc4);
                rb[i] = *(const float4*)(W + (size_t)(bn + row) * Ec + (ks + 1) * 32 + lc4);
            }
        }
        #pragma unroll
        for (int k8 = 0; k8 < 4; k8++) {
            uint32_t af[4][4], bf[4][2];
            #pragma unroll
            for (int mt = 0; mt < 4; mt++)
                ldsm4(af[mt], sA[cur] + (uint32_t)(((aRow + mt * 16) * 36 + k8 * 8 + aCol) * 4));
            #pragma unroll
            for (int np = 0; np < 2; np++) {
                uint32_t t4[4];
                ldsm4(t4, sB[cur] + (uint32_t)(((bRow + np * 16) * 36 + k8 * 8 + bCol) * 4));
                bf[2*np][0] = t4[0]; bf[2*np][1] = t4[1];
                bf[2*np+1][0] = t4[2]; bf[2*np+1][1] = t4[3];
            }
            #pragma unroll
            for (int mt = 0; mt < 4; mt++)
                #pragma unroll
                for (int nt = 0; nt < 4; nt++)
                    mma_tf32(c[mt][nt], af[mt], bf[nt]);
        }
        if (ks < 31) {
            #pragma unroll
            for (int i = 0; i < 4; i++) {
                int row = lrw + i * 32;
                *(uint4*)&Abuf[cur ^ 1][row * 36 + lc4] =
                    make_uint4(cvt_tf32(ra[i].x), cvt_tf32(ra[i].y), cvt_tf32(ra[i].z), cvt_tf32(ra[i].w));
                *(uint4*)&Bbuf[cur ^ 1][row * 36 + lc4] =
                    make_uint4(cvt_tf32(rb[i].x), cvt_tf32(rb[i].y), cvt_tf32(rb[i].z), cvt_tf32(rb[i].w));
            }
        }
        __syncthreads();
    }

    const int lrow = lane >> 2;
    const int lk   = lane & 3;
    #pragma unroll
    for (int mt = 0; mt < 4; mt++) {
        #pragma unroll
        for (int half = 0; half < 2; half++) {
            int row = bm + wrow * 64 + mt * 16 + lrow + half * 8;
            #pragma unroll
            for (int nt = 0; nt < 4; nt++) {
                int col = bn + wcol * 32 + nt * 8 + lk * 2;
                float v0 = c[mt][nt][half * 2];
                float v1 = c[mt][nt][half * 2 + 1];
                if (MODE == 0) {
                    int b = row >> 11, t = row & 2047;
                    int h = col >> 6, d = col & 63;
                    *(float2*)&dst[(((size_t)(b * Hc + h)) * Tc + t) * HDc + d] =
                        make_float2((v0 + bias[col]) * scale, (v1 + bias[col + 1]) * scale);
                } else {
                    *(float2*)&dst[(size_t)row * Ec + col] =
                        make_float2(v0 + bias[col], v1 + bias[col + 1]);
                }
            }
        }
    }
}

// ---------------------------------------------------------------------------
// Score (single-stage, K=64): S = Q @ K^T per (bh), mask -> g_p, rowmax atomics.
// smem: Qs[128][68], Ks[128][68]  (stride 68: 16B-aligned rows, conflict-free)
// ---------------------------------------------------------------------------
__global__ void __launch_bounds__(256, 2) score_ss(
    const unsigned char* __restrict__ am, const unsigned char* __restrict__ kpm)
{
    extern __shared__ uint32_t ds[];
    uint32_t* Qs = ds;               // 128*68
    uint32_t* Ks = ds + 128 * 68;

    const int tid  = threadIdx.x;
    const int wid  = tid >> 5;
    const int lane = tid & 31;
    const int wrow = wid >> 2;
    const int wcol = wid & 3;
    const int bm = blockIdx.y * 128;
    const int bn = blockIdx.x * 128;
    const int bh = blockIdx.z;

    const float* Q = g_q + (size_t)bh * Tc * HDc;
    const float* K = g_k + (size_t)bh * Sc * HDc;

    // load full 128x64 Q and K tiles (8 float4 per thread each)
    #pragma unroll
    for (int i = 0; i < 8; i++) {
        int flat = tid + i * 256;
        int row = flat >> 4, c4 = (flat & 15) * 4;
        float4 q = *(const float4*)(Q + (size_t)(bm + row) * HDc + c4);
        float4 k = *(const float4*)(K + (size_t)(bn + row) * HDc + c4);
        *(uint4*)&Qs[row * 68 + c4] = make_uint4(cvt_tf32(q.x), cvt_tf32(q.y),
                                                 cvt_tf32(q.z), cvt_tf32(q.w));
        *(uint4*)&Ks[row * 68 + c4] = make_uint4(cvt_tf32(k.x), cvt_tf32(k.y),
                                                 cvt_tf32(k.z), cvt_tf32(k.w));
    }
    __syncthreads();

    float c[4][4][4];
    #pragma unroll
    for (int i = 0; i < 4; i++)
        #pragma unroll
        for (int j = 0; j < 4; j++)
            #pragma unroll
            for (int u = 0; u < 4; u++) c[i][j][u] = 0.f;

    const int aRow = wrow * 64 + (lane & 7) + ((lane >> 3) & 1) * 8;
    const int aCol = (lane >> 4) * 4;
    const int bRow = wcol * 32 + ((lane >> 4) * 8) + (lane & 7);
    const int bCol = ((lane >> 3) & 1) * 4;
    const uint32_t sQ = smem_u32(Qs);
    const uint32_t sK = smem_u32(Ks);

    #pragma unroll
    for (int k8 = 0; k8 < 8; k8++) {
        uint32_t af[4][4], bf[4][2];
        #pragma unroll
        for (int mt = 0; mt < 4; mt++)
            ldsm4(af[mt], sQ + (uint32_t)(((aRow + mt * 16) * 68 + k8 * 8 + aCol) * 4));
        #pragma unroll
        for (int np = 0; np < 2; np++) {
            uint32_t t4[4];
            ldsm4(t4, sK + (uint32_t)(((bRow + np * 16) * 68 + k8 * 8 + bCol) * 4));
            bf[2*np][0] = t4[0]; bf[2*np][1] = t4[1];
            bf[2*np+1][0] = t4[2]; bf[2*np+1][1] = t4[3];
        }
        #pragma unroll
        for (int mt = 0; mt < 4; mt++)
            #pragma unroll
            for (int nt = 0; nt < 4; nt++)
                mma_tf32(c[mt][nt], af[mt], bf[nt]);
    }

    const int lrow = lane >> 2;
    const int lk   = lane & 3;
    const int b = bh >> 4;
    #pragma unroll
    for (int mt = 0; mt < 4; mt++) {
        #pragma unroll
        for (int half = 0; half < 2; half++) {
            int row = bm + wrow * 64 + mt * 16 + lrow + half * 8;
            float rmax = -1e30f;
            #pragma unroll
            for (int nt = 0; nt < 4; nt++) {
                int col = bn + wcol * 32 + nt * 8 + lk * 2;
                float v0 = c[mt][nt][half * 2];
                float v1 = c[mt][nt][half * 2 + 1];
                if (am[(size_t)row * Sc + col] | kpm[(size_t)b * Sc + col]) v0 = 1e-10f;
                if (am[(size_t)row * Sc + col + 1] | kpm[(size_t)b * Sc + col + 1]) v1 = 1e-10f;
                *(float2*)&g_p[((size_t)bh * Tc + row) * Sc + col] = make_float2(v0, v1);
                rmax = fmaxf(rmax, fmaxf(v0, v1));
            }
            rmax = fmaxf(rmax, __shfl_xor_sync(0xffffffffu, rmax, 1));
            rmax = fmaxf(rmax, __shfl_xor_sync(0xffffffffu, rmax, 2));
            if (lk == 0) atomicMaxF(&g_m[(size_t)bh * Tc + row], rmax);
        }
    }
}

// ---------------------------------------------------------------------------
// pv_prob: per (bh, t-tile 128).  p = exp(score - m); rowsum; O = (p @ V)/sum;
// writes g_o and c = m + log(sum).  8 warps, each owns 16 t-rows, all 64 d.
// ---------------------------------------------------------------------------
__global__ void __launch_bounds__(256) pv_prob()
{
    extern __shared__ uint32_t dsm[];
    uint32_t* Asm = dsm;                 // [128][132] raw fp32 scores
    uint32_t* Vsm = dsm + 128 * 132;     // [128][72]  tf32 V (rows=s, cols=d)

    const int tid  = threadIdx.x;
    const int wid  = tid >> 5;
    const int lane = tid & 31;
    const int lrow = lane >> 2;
    const int lk   = lane & 3;
    const int bh = blockIdx.y;
    const int b = bh >> 4, h = bh & 15;
    const int tbase = blockIdx.x * 128;
    const int wt = wid * 16;

    const float* P = g_p + ((size_t)bh * Tc + tbase) * Sc;
    const float* V = g_v + (size_t)bh * Sc * HDc;

    const int r_lo = wt + lrow, r_hi = wt + lrow + 8;
    const float m_lo = decodeOrd(g_m[(size_t)bh * Tc + tbase + r_lo]);
    const float m_hi = decodeOrd(g_m[(size_t)bh * Tc + tbase + r_hi]);
    float sum_lo = 0.f, sum_hi = 0.f;

    float acc[8][4];
    #pragma unroll
    for (int j = 0; j < 8; j++)
        #pragma unroll
        for (int u = 0; u < 4; u++) acc[j][u] = 0.f;

    const int aRow = wt + (lane & 7) + ((lane >> 3) & 1) * 8;
    const int aCol = (lane >> 4) * 4;
    const uint32_t sA = smem_u32(Asm);

    for (int s0 = 0; s0 < Sc; s0 += 128) {
        #pragma unroll
        for (int i = 0; i < 16; i++) {
            int flat = tid + i * 256;
            int row = flat >> 5, c4 = (flat & 31) * 4;
            *(float4*)&Asm[row * 132 + c4] =
                *(const float4*)(P + (size_t)row * Sc + s0 + c4);
        }
        #pragma unroll
        for (int i = 0; i < 8; i++) {
            int flat = tid + i * 256;
            int row = flat >> 4, c4 = (flat & 15) * 4;
            float4 v = *(const float4*)(V + (size_t)(s0 + row) * HDc + c4);
            *(uint4*)&Vsm[row * 72 + c4] = make_uint4(cvt_tf32(v.x), cvt_tf32(v.y),
                                                      cvt_tf32(v.z), cvt_tf32(v.w));
        }
        __syncthreads();

        #pragma unroll
        for (int k8 = 0; k8 < 16; k8++) {
            uint32_t a[4];
            ldsm4(a, sA + (uint32_t)((aRow * 132 + k8 * 8 + aCol) * 4));
            float p0 = __expf(__uint_as_float(a[0]) - m_lo);
            float p1 = __expf(__uint_as_float(a[1]) - m_hi);
            float p2 = __expf(__uint_as_float(a[2]) - m_lo);
            float p3 = __expf(__uint_as_float(a[3]) - m_hi);
            sum_lo += p0 + p2;
            sum_hi += p1 + p3;
            uint32_t pa[4] = {cvt_tf32(p0), cvt_tf32(p1), cvt_tf32(p2), cvt_tf32(p3)};
            #pragma unroll
            for (int nt = 0; nt < 8; nt++) {
                uint32_t bfr[2];
                bfr[0] = Vsm[(k8 * 8 + lk) * 72 + nt * 8 + lrow];
                bfr[1] = Vsm[(k8 * 8 + lk + 4) * 72 + nt * 8 + lrow];
                mma_tf32(acc[nt], pa, bfr);
            }
        }
        __syncthreads();
    }

    sum_lo += __shfl_xor_sync(0xffffffffu, sum_lo, 1);
    sum_lo += __shfl_xor_sync(0xffffffffu, sum_lo, 2);
    sum_hi += __shfl_xor_sync(0xffffffffu, sum_hi, 1);
    sum_hi += __shfl_xor_sync(0xffffffffu, sum_hi, 2);
    const float inv_lo = 1.0f / sum_lo;
    const float inv_hi = 1.0f / sum_hi;

    const int t_lo = tbase + r_lo, t_hi = tbase + r_hi;
    #pragma unroll
    for (int nt = 0; nt < 8; nt++) {
        int d = nt * 8 + lk * 2;
        *(float2*)&g_o[(((size_t)b * Tc + t_lo) * Hc + h) * HDc + d] =
            make_float2(acc[nt][0] * inv_lo, acc[nt][1] * inv_lo);
        *(float2*)&g_o[(((size_t)b * Tc + t_hi) * Hc + h) * HDc + d] =
            make_float2(acc[nt][2] * inv_hi, acc[nt][3] * inv_hi);
    }
    if (lk == 0) {
        g_c[(size_t)bh * Tc + t_lo] = m_lo + __logf(sum_lo);
        g_c[(size_t)bh * Tc + t_hi] = m_hi + __logf(sum_hi);
    }
}

// ---------------------------------------------------------------------------
// headmax: attn_max[b,t,s] = exp(max_h (score[b,h,t,s] - c[b,h,t]))
// ---------------------------------------------------------------------------
__global__ void __launch_bounds__(256) headmax_kernel(float* __restrict__ out2)
{
    size_t i4 = (size_t)blockIdx.x * 256 + threadIdx.x;
    size_t sq = i4 % (Sc / 4);
    size_t bt = i4 / (Sc / 4);
    size_t b = bt >> 11, t = bt & 2047;
    size_t s = sq * 4;

    float4 best = make_float4(-1e30f, -1e30f, -1e30f, -1e30f);
    #pragma unroll
    for (int h = 0; h < Hc; h++) {
        size_t bh = b * Hc + h;
        float ch = g_c[bh * Tc + t];
        float4 sc = *(const float4*)&g_p[(bh * Tc + t) * Sc + s];
        best.x = fmaxf(best.x, sc.x - ch);
        best.y = fmaxf(best.y, sc.y - ch);
        best.z = fmaxf(best.z, sc.z - ch);
        best.w = fmaxf(best.w, sc.w - ch);
    }
    *(float4*)&out2[bt * Sc + s] =
        make_float4(__expf(best.x), __expf(best.y), __expf(best.z), __expf(best.w));
}

// ---------------------------------------------------------------------------
extern "C" void kernel_launch(void* const* d_in, const int* in_sizes, int n_in,
                              void* d_out, int out_size)
{
    const float* query = (const float*)d_in[0];
    const float* key   = (const float*)d_in[1];
    const float* value = (const float*)d_in[2];
    const unsigned char* kpm = (const unsigned char*)d_in[3];
    const unsigned char* am  = (const unsigned char*)d_in[4];
    const float* Wq = (const float*)d_in[5];
    const float* bq = (const float*)d_in[6];
    const float* Wk = (const float*)d_in[7];
    const float* bk = (const float*)d_in[8];
    const float* Wv = (const float*)d_in[9];
    const float* bv = (const float*)d_in[10];
    const float* Wo = (const float*)d_in[11];
    const float* bo = (const float*)d_in[12];

    float* out      = (float*)d_out;
    float* attn_max = (float*)d_out + (size_t)Bc * Tc * Ec;

    float *po;
    cudaGetSymbolAddress((void**)&po, g_o);

    const int GEMM_SMEM  = 4 * 128 * 36 * 4;              // 73728 (double buffer)
    const int SCORE_SMEM = 2 * 128 * 68 * 4;              // 69632
    const int PV_SMEM    = (128 * 132 + 128 * 72) * 4;    // 104448
    cudaFuncSetAttribute(gemm_db<0>, cudaFuncAttributeMaxDynamicSharedMemorySize, GEMM_SMEM);
    cudaFuncSetAttribute(gemm_db<3>, cudaFuncAttributeMaxDynamicSharedMemorySize, GEMM_SMEM);
    cudaFuncSetAttribute(score_ss,   cudaFuncAttributeMaxDynamicSharedMemorySize, SCORE_SMEM);
    cudaFuncSetAttribute(pv_prob,    cudaFuncAttributeMaxDynamicSharedMemorySize, PV_SMEM);

    dim3 thr(256);

    initm_kernel<<<dim3((Bc * Hc * Tc + 255) / 256), thr>>>();

    // Batched Q/K/V projections (grid.z = 0,1,2)
    gemm_db<0><<<dim3(Ec / 128, (Bc * Tc) / 128, 3), thr, GEMM_SMEM>>>(
        query, key, value, Wq, Wk, Wv, bq, bk, bv, nullptr);

    // Scores: masked raw scores into g_p + atomic row max into g_m
    score_ss<<<dim3(Sc / 128, Tc / 128, Bc * Hc), thr, SCORE_SMEM>>>(am, kpm);

    // Fused softmax + P@V
    pv_prob<<<dim3(Tc / 128, Bc * Hc), thr, PV_SMEM>>>();

    // attn_max output
    headmax_kernel<<<dim3((unsigned)(((size_t)Bc * Tc * Sc / 4) / 256)), thr>>>(attn_max);

    // Output projection
    gemm_db<3><<<dim3(Ec / 128, (Bc * Tc) / 128, 1), thr, GEMM_SMEM>>>(
        po, nullptr, nullptr, Wo, nullptr, nullptr, bo, nullptr, nullptr, out);
}

// round 9
// speedup vs baseline: 2.8242x; 1.0775x over previous
#include <cuda_runtime.h>
#include <cstdint>
#include <math.h>

#define Bc 2
#define Tc 2048
#define Sc 2048
#define Ec 1024
#define Hc 16
#define HDc 64
#define QSCALE 0.125f

// Scratch (__device__ globals; allocation-free)
__device__ float g_q[(size_t)Bc*Hc*Tc*HDc];   // [bh,t,d]
__device__ float g_k[(size_t)Bc*Hc*Sc*HDc];   // [bh,s,d]
__device__ float g_v[(size_t)Bc*Hc*Sc*HDc];   // [bh,s,d]
__device__ float g_o[(size_t)Bc*Tc*Ec];       // [b,t,h,d]  attn out pre-Wo
__device__ float g_p[(size_t)Bc*Hc*Tc*Sc];    // [bh,t,s]   raw masked scores (512 MB)
__device__ float g_c[Bc*Hc*Tc];               // m + log(sum)

__device__ __forceinline__ uint32_t cvt_tf32(float f) {
    uint32_t r; asm("cvt.rna.tf32.f32 %0, %1;" : "=r"(r) : "f"(f)); return r;
}
__device__ __forceinline__ uint32_t smem_u32(const void* p) {
    uint32_t a;
    asm("{ .reg .u64 t; cvta.to.shared.u64 t, %1; cvt.u32.u64 %0, t; }" : "=r"(a) : "l"(p));
    return a;
}
__device__ __forceinline__ void mma_tf32(float c[4], const uint32_t a[4], const uint32_t b[2]) {
    asm volatile(
        "mma.sync.aligned.m16n8k8.row.col.f32.tf32.tf32.f32 "
        "{%0,%1,%2,%3}, {%4,%5,%6,%7}, {%8,%9}, {%0,%1,%2,%3};"
        : "+f"(c[0]), "+f"(c[1]), "+f"(c[2]), "+f"(c[3])
        : "r"(a[0]), "r"(a[1]), "r"(a[2]), "r"(a[3]), "r"(b[0]), "r"(b[1]));
}
__device__ __forceinline__ void mma_f16(float c[4], const uint32_t a[4], uint32_t b0, uint32_t b1) {
    asm volatile(
        "mma.sync.aligned.m16n8k16.row.col.f32.f16.f16.f32 "
        "{%0,%1,%2,%3}, {%4,%5,%6,%7}, {%8,%9}, {%0,%1,%2,%3};"
        : "+f"(c[0]), "+f"(c[1]), "+f"(c[2]), "+f"(c[3])
        : "r"(a[0]), "r"(a[1]), "r"(a[2]), "r"(a[3]), "r"(b0), "r"(b1));
}
__device__ __forceinline__ void ldsm4(uint32_t r[4], uint32_t addr) {
    asm volatile("ldmatrix.sync.aligned.m8n8.x4.shared.b16 {%0,%1,%2,%3}, [%4];"
        : "=r"(r[0]), "=r"(r[1]), "=r"(r[2]), "=r"(r[3]) : "r"(addr));
}
__device__ __forceinline__ void ldsm4t(uint32_t r[4], uint32_t addr) {
    asm volatile("ldmatrix.sync.aligned.m8n8.x4.trans.shared.b16 {%0,%1,%2,%3}, [%4];"
        : "=r"(r[0]), "=r"(r[1]), "=r"(r[2]), "=r"(r[3]) : "r"(addr));
}
__device__ __forceinline__ uint32_t pack_f16(float lo, float hi) {
    uint32_t r; asm("cvt.rn.f16x2.f32 %0, %1, %2;" : "=r"(r) : "f"(hi), "f"(lo)); return r;
}

// ---------------------------------------------------------------------------
// Double-buffered tf32 GEMM:  C = A[M,1024] @ W[1024,1024]^T (+bias)
// MODE 0: batched QKV projection (blockIdx.z selects q/k/v) -> g_q/g_k/g_v
// MODE 3: output projection (flat [row, col] out)
// ---------------------------------------------------------------------------
template<int MODE>
__global__ void __launch_bounds__(256, 2) gemm_db(
    const float* __restrict__ A0, const float* __restrict__ A1, const float* __restrict__ A2,
    const float* __restrict__ W0, const float* __restrict__ W1, const float* __restrict__ W2,
    const float* __restrict__ bias0, const float* __restrict__ bias1, const float* __restrict__ bias2,
    float* __restrict__ Cout)
{
    extern __shared__ uint32_t ds[];
    uint32_t* const Abuf[2] = { ds,         ds + 9216 };
    uint32_t* const Bbuf[2] = { ds + 4608,  ds + 13824 };

    const int tid  = threadIdx.x;
    const int wid  = tid >> 5;
    const int lane = tid & 31;
    const int wrow = wid >> 2;
    const int wcol = wid & 3;
    const int bm = blockIdx.y * 128;
    const int bn = blockIdx.x * 128;
    const int z  = blockIdx.z;

    const float* A; const float* W; const float* bias; float scale; float* dst;
    if (MODE == 0) {
        A    = (z == 0) ? A0 : (z == 1) ? A1 : A2;
        W    = (z == 0) ? W0 : (z == 1) ? W1 : W2;
        bias = (z == 0) ? bias0 : (z == 1) ? bias1 : bias2;
        scale = (z == 0) ? QSCALE : 1.0f;
        dst  = (z == 0) ? g_q : (z == 1) ? g_k : g_v;
    } else {
        A = A0; W = W0; bias = bias0; scale = 1.0f; dst = Cout;
    }

    float c[4][4][4];
    #pragma unroll
    for (int i = 0; i < 4; i++)
        #pragma unroll
        for (int j = 0; j < 4; j++)
            #pragma unroll
            for (int u = 0; u < 4; u++) c[i][j][u] = 0.f;

    const int aRow = wrow * 64 + (lane & 7) + ((lane >> 3) & 1) * 8;
    const int aCol = (lane >> 4) * 4;
    const int bRow = wcol * 32 + ((lane >> 4) * 8) + (lane & 7);
    const int bCol = ((lane >> 3) & 1) * 4;
    const uint32_t sA[2] = { smem_u32(Abuf[0]), smem_u32(Abuf[1]) };
    const uint32_t sB[2] = { smem_u32(Bbuf[0]), smem_u32(Bbuf[1]) };

    const int lrw = tid >> 3;
    const int lc4 = (tid & 7) * 4;

    float4 ra[4], rb[4];
    #pragma unroll
    for (int i = 0; i < 4; i++) {
        int row = lrw + i * 32;
        ra[i] = *(const float4*)(A + (size_t)(bm + row) * Ec + lc4);
        rb[i] = *(const float4*)(W + (size_t)(bn + row) * Ec + lc4);
    }
    #pragma unroll
    for (int i = 0; i < 4; i++) {
        int row = lrw + i * 32;
        *(uint4*)&Abuf[0][row * 36 + lc4] = make_uint4(cvt_tf32(ra[i].x), cvt_tf32(ra[i].y),
                                                       cvt_tf32(ra[i].z), cvt_tf32(ra[i].w));
        *(uint4*)&Bbuf[0][row * 36 + lc4] = make_uint4(cvt_tf32(rb[i].x), cvt_tf32(rb[i].y),
                                                       cvt_tf32(rb[i].z), cvt_tf32(rb[i].w));
    }
    __syncthreads();

    for (int ks = 0; ks < 32; ks++) {
        const int cur = ks & 1;
        if (ks < 31) {
            #pragma unroll
            for (int i = 0; i < 4; i++) {
                int row = lrw + i * 32;
                ra[i] = *(const float4*)(A + (size_t)(bm + row) * Ec + (ks + 1) * 32 + lc4);
                rb[i] = *(const float4*)(W + (size_t)(bn + row) * Ec + (ks + 1) * 32 + lc4);
            }
        }
        #pragma unroll
        for (int k8 = 0; k8 < 4; k8++) {
            uint32_t af[4][4], bf[4][2];
            #pragma unroll
            for (int mt = 0; mt < 4; mt++)
                ldsm4(af[mt], sA[cur] + (uint32_t)(((aRow + mt * 16) * 36 + k8 * 8 + aCol) * 4));
            #pragma unroll
            for (int np = 0; np < 2; np++) {
                uint32_t t4[4];
                ldsm4(t4, sB[cur] + (uint32_t)(((bRow + np * 16) * 36 + k8 * 8 + bCol) * 4));
                bf[2*np][0] = t4[0]; bf[2*np][1] = t4[1];
                bf[2*np+1][0] = t4[2]; bf[2*np+1][1] = t4[3];
            }
            #pragma unroll
            for (int mt = 0; mt < 4; mt++)
                #pragma unroll
                for (int nt = 0; nt < 4; nt++)
                    mma_tf32(c[mt][nt], af[mt], bf[nt]);
        }
        if (ks < 31) {
            #pragma unroll
            for (int i = 0; i < 4; i++) {
                int row = lrw + i * 32;
                *(uint4*)&Abuf[cur ^ 1][row * 36 + lc4] =
                    make_uint4(cvt_tf32(ra[i].x), cvt_tf32(ra[i].y), cvt_tf32(ra[i].z), cvt_tf32(ra[i].w));
                *(uint4*)&Bbuf[cur ^ 1][row * 36 + lc4] =
                    make_uint4(cvt_tf32(rb[i].x), cvt_tf32(rb[i].y), cvt_tf32(rb[i].z), cvt_tf32(rb[i].w));
            }
        }
        __syncthreads();
    }

    const int lrow = lane >> 2;
    const int lk   = lane & 3;
    #pragma unroll
    for (int mt = 0; mt < 4; mt++) {
        #pragma unroll
        for (int half = 0; half < 2; half++) {
            int row = bm + wrow * 64 + mt * 16 + lrow + half * 8;
            #pragma unroll
            for (int nt = 0; nt < 4; nt++) {
                int col = bn + wcol * 32 + nt * 8 + lk * 2;
                float v0 = c[mt][nt][half * 2];
                float v1 = c[mt][nt][half * 2 + 1];
                if (MODE == 0) {
                    int b = row >> 11, t = row & 2047;
                    int h = col >> 6, d = col & 63;
                    *(float2*)&dst[(((size_t)(b * Hc + h)) * Tc + t) * HDc + d] =
                        make_float2((v0 + bias[col]) * scale, (v1 + bias[col + 1]) * scale);
                } else {
                    *(float2*)&dst[(size_t)row * Ec + col] =
                        make_float2(v0 + bias[col], v1 + bias[col + 1]);
                }
            }
        }
    }
}

// ---------------------------------------------------------------------------
// attn_fused: per (bh, 64-row t-tile). Flash-style online softmax.
//   S = Q@K^T (tf32 mma, Q frags in regs), mask, raw S -> g_p,
//   online max/rescale, p = exp(S - m) packed fp16, O += P@V (fp16 mma).
// Writes g_o = O / sum and g_c = m + log(sum).
// 128 threads / 4 warps; warp owns 16 t-rows x all 64 d.
// ---------------------------------------------------------------------------
__global__ void __launch_bounds__(128, 3) attn_fused(
    const unsigned char* __restrict__ am, const unsigned char* __restrict__ kpm)
{
    __shared__ uint32_t Ks[64 * 68];   // Q staging, then K tiles (tf32)
    __shared__ uint32_t Vs[64 * 36];   // V tiles (fp16x2, 72-half row stride)

    const int tid  = threadIdx.x;
    const int w    = tid >> 5;
    const int lane = tid & 31;
    const int lrow = lane >> 2;
    const int lk   = lane & 3;
    const int tbase = blockIdx.x * 64;
    const int bh = blockIdx.y;
    const int b = bh >> 4, h = bh & 15;

    const float* Q  = g_q + (size_t)bh * Tc * HDc;
    const float* Kg = g_k + (size_t)bh * Sc * HDc;
    const float* Vg = g_v + (size_t)bh * Sc * HDc;

    const uint32_t sK = smem_u32(Ks);
    const uint32_t sV = smem_u32(Vs);

    // ---- stage Q tile (64x64) and load A-fragments into registers ----
    #pragma unroll
    for (int i = 0; i < 8; i++) {
        int flat = tid + i * 128;
        int row = flat >> 4, c4 = (flat & 15) * 4;
        float4 q = *(const float4*)(Q + (size_t)(tbase + row) * HDc + c4);
        *(uint4*)&Ks[row * 68 + c4] = make_uint4(cvt_tf32(q.x), cvt_tf32(q.y),
                                                 cvt_tf32(q.z), cvt_tf32(q.w));
    }
    __syncthreads();
    uint32_t aQ[8][4];
    const int aRow = w * 16 + (lane & 7) + ((lane >> 3) & 1) * 8;
    const int aCol = (lane >> 4) * 4;
    #pragma unroll
    for (int k8 = 0; k8 < 8; k8++)
        ldsm4(aQ[k8], sK + (uint32_t)((aRow * 68 + k8 * 8 + aCol) * 4));
    __syncthreads();

    float Oa[8][4];
    #pragma unroll
    for (int i = 0; i < 8; i++)
        #pragma unroll
        for (int u = 0; u < 4; u++) Oa[i][u] = 0.f;
    float m_lo = -1e30f, m_hi = -1e30f, s_lo = 0.f, s_hi = 0.f;

    const int t_lo = tbase + w * 16 + lrow;
    const int t_hi = t_lo + 8;

    for (int s0 = 0; s0 < Sc; s0 += 64) {
        // ---- load K (tf32) and V (fp16) tiles ----
        #pragma unroll
        for (int i = 0; i < 8; i++) {
            int flat = tid + i * 128;
            int row = flat >> 4, c4 = (flat & 15) * 4;
            float4 kv = *(const float4*)(Kg + (size_t)(s0 + row) * HDc + c4);
            *(uint4*)&Ks[row * 68 + c4] = make_uint4(cvt_tf32(kv.x), cvt_tf32(kv.y),
                                                     cvt_tf32(kv.z), cvt_tf32(kv.w));
            float4 vv = *(const float4*)(Vg + (size_t)(s0 + row) * HDc + c4);
            Vs[row * 36 + (c4 >> 1)]     = pack_f16(vv.x, vv.y);
            Vs[row * 36 + (c4 >> 1) + 1] = pack_f16(vv.z, vv.w);
        }
        __syncthreads();

        // ---- S = Q @ K^T ----
        float S[8][4];
        #pragma unroll
        for (int nt = 0; nt < 8; nt++)
            #pragma unroll
            for (int u = 0; u < 4; u++) S[nt][u] = 0.f;
        #pragma unroll
        for (int k8 = 0; k8 < 8; k8++) {
            uint32_t bf[8][2];
            #pragma unroll
            for (int np = 0; np < 4; np++) {
                uint32_t t4[4];
                int brow = np * 16 + ((lane >> 4) * 8) + (lane & 7);
                ldsm4(t4, sK + (uint32_t)((brow * 68 + k8 * 8 + ((lane >> 3) & 1) * 4) * 4));
                bf[2*np][0] = t4[0]; bf[2*np][1] = t4[1];
                bf[2*np+1][0] = t4[2]; bf[2*np+1][1] = t4[3];
            }
            #pragma unroll
            for (int nt = 0; nt < 8; nt++)
                mma_tf32(S[nt], aQ[k8], bf[nt]);
        }

        // ---- mask, raw-score write, tile max ----
        float tmax_lo = -1e30f, tmax_hi = -1e30f;
        #pragma unroll
        for (int nt = 0; nt < 8; nt++) {
            int col = s0 + nt * 8 + lk * 2;
            uchar2 a0 = *(const uchar2*)&am[(size_t)t_lo * Sc + col];
            uchar2 a1 = *(const uchar2*)&am[(size_t)t_hi * Sc + col];
            uchar2 kp = *(const uchar2*)&kpm[(size_t)b * Sc + col];
            if (a0.x | kp.x) S[nt][0] = 1e-10f;
            if (a0.y | kp.y) S[nt][1] = 1e-10f;
            if (a1.x | kp.x) S[nt][2] = 1e-10f;
            if (a1.y | kp.y) S[nt][3] = 1e-10f;
            *(float2*)&g_p[((size_t)bh * Tc + t_lo) * Sc + col] = make_float2(S[nt][0], S[nt][1]);
            *(float2*)&g_p[((size_t)bh * Tc + t_hi) * Sc + col] = make_float2(S[nt][2], S[nt][3]);
            tmax_lo = fmaxf(tmax_lo, fmaxf(S[nt][0], S[nt][1]));
            tmax_hi = fmaxf(tmax_hi, fmaxf(S[nt][2], S[nt][3]));
        }
        tmax_lo = fmaxf(tmax_lo, __shfl_xor_sync(0xffffffffu, tmax_lo, 1));
        tmax_lo = fmaxf(tmax_lo, __shfl_xor_sync(0xffffffffu, tmax_lo, 2));
        tmax_hi = fmaxf(tmax_hi, __shfl_xor_sync(0xffffffffu, tmax_hi, 1));
        tmax_hi = fmaxf(tmax_hi, __shfl_xor_sync(0xffffffffu, tmax_hi, 2));

        // ---- online rescale ----
        float mnew_lo = fmaxf(m_lo, tmax_lo);
        float mnew_hi = fmaxf(m_hi, tmax_hi);
        float f_lo = __expf(m_lo - mnew_lo);
        float f_hi = __expf(m_hi - mnew_hi);
        m_lo = mnew_lo; m_hi = mnew_hi;
        s_lo *= f_lo;   s_hi *= f_hi;
        #pragma unroll
        for (int nd = 0; nd < 8; nd++) {
            Oa[nd][0] *= f_lo; Oa[nd][1] *= f_lo;
            Oa[nd][2] *= f_hi; Oa[nd][3] *= f_hi;
        }

        // ---- p = exp(S - m), sums, fp16 pack (C-frag == fp16 A-frag layout) ----
        uint32_t aP[4][4];
        #pragma unroll
        for (int nt = 0; nt < 8; nt++) {
            float p0 = __expf(S[nt][0] - m_lo);
            float p1 = __expf(S[nt][1] - m_lo);
            float p2 = __expf(S[nt][2] - m_hi);
            float p3 = __expf(S[nt][3] - m_hi);
            s_lo += p0 + p1;
            s_hi += p2 + p3;
            int kk = nt >> 1, hi = (nt & 1) * 2;
            aP[kk][hi]     = pack_f16(p0, p1);
            aP[kk][hi + 1] = pack_f16(p2, p3);
        }

        // ---- O += P @ V  (fp16 m16n8k16, B via ldmatrix.trans) ----
        #pragma unroll
        for (int kk = 0; kk < 4; kk++) {
            int vrow = kk * 16 + (lane & 7) + ((lane >> 3) & 1) * 8;
            #pragma unroll
            for (int nd16 = 0; nd16 < 4; nd16++) {
                uint32_t t4[4];
                int vcol = nd16 * 16 + (lane >> 4) * 8;
                ldsm4t(t4, sV + (uint32_t)((vrow * 72 + vcol) * 2));
                mma_f16(Oa[nd16 * 2],     aP[kk], t4[0], t4[1]);
                mma_f16(Oa[nd16 * 2 + 1], aP[kk], t4[2], t4[3]);
            }
        }
        __syncthreads();
    }

    // ---- epilogue ----
    float r_lo = s_lo, r_hi = s_hi;
    r_lo += __shfl_xor_sync(0xffffffffu, r_lo, 1);
    r_lo += __shfl_xor_sync(0xffffffffu, r_lo, 2);
    r_hi += __shfl_xor_sync(0xffffffffu, r_hi, 1);
    r_hi += __shfl_xor_sync(0xffffffffu, r_hi, 2);
    const float inv_lo = 1.0f / r_lo;
    const float inv_hi = 1.0f / r_hi;

    #pragma unroll
    for (int nd = 0; nd < 8; nd++) {
        int d = nd * 8 + lk * 2;
        *(float2*)&g_o[(((size_t)b * Tc + t_lo) * Hc + h) * HDc + d] =
            make_float2(Oa[nd][0] * inv_lo, Oa[nd][1] * inv_lo);
        *(float2*)&g_o[(((size_t)b * Tc + t_hi) * Hc + h) * HDc + d] =
            make_float2(Oa[nd][2] * inv_hi, Oa[nd][3] * inv_hi);
    }
    if (lk == 0) {
        g_c[(size_t)bh * Tc + t_lo] = m_lo + __logf(r_lo);
        g_c[(size_t)bh * Tc + t_hi] = m_hi + __logf(r_hi);
    }
}

// ---------------------------------------------------------------------------
// headmax: attn_max[b,t,s] = exp(max_h (score[b,h,t,s] - c[b,h,t]))
// ---------------------------------------------------------------------------
__global__ void __launch_bounds__(256) headmax_kernel(float* __restrict__ out2)
{
    size_t i4 = (size_t)blockIdx.x * 256 + threadIdx.x;
    size_t sq = i4 % (Sc / 4);
    size_t bt = i4 / (Sc / 4);
    size_t b = bt >> 11, t = bt & 2047;
    size_t s = sq * 4;

    float4 best = make_float4(-1e30f, -1e30f, -1e30f, -1e30f);
    #pragma unroll
    for (int h = 0; h < Hc; h++) {
        size_t bh = b * Hc + h;
        float ch = g_c[bh * Tc + t];
        float4 sc = *(const float4*)&g_p[(bh * Tc + t) * Sc + s];
        best.x = fmaxf(best.x, sc.x - ch);
        best.y = fmaxf(best.y, sc.y - ch);
        best.z = fmaxf(best.z, sc.z - ch);
        best.w = fmaxf(best.w, sc.w - ch);
    }
    *(float4*)&out2[bt * Sc + s] =
        make_float4(__expf(best.x), __expf(best.y), __expf(best.z), __expf(best.w));
}

// ---------------------------------------------------------------------------
extern "C" void kernel_launch(void* const* d_in, const int* in_sizes, int n_in,
                              void* d_out, int out_size)
{
    const float* query = (const float*)d_in[0];
    const float* key   = (const float*)d_in[1];
    const float* value = (const float*)d_in[2];
    const unsigned char* kpm = (const unsigned char*)d_in[3];
    const unsigned char* am  = (const unsigned char*)d_in[4];
    const float* Wq = (const float*)d_in[5];
    const float* bq = (const float*)d_in[6];
    const float* Wk = (const float*)d_in[7];
    const float* bk = (const float*)d_in[8];
    const float* Wv = (const float*)d_in[9];
    const float* bv = (const float*)d_in[10];
    const float* Wo = (const float*)d_in[11];
    const float* bo = (const float*)d_in[12];

    float* out      = (float*)d_out;
    float* attn_max = (float*)d_out + (size_t)Bc * Tc * Ec;

    float *po;
    cudaGetSymbolAddress((void**)&po, g_o);

    const int GEMM_SMEM = 4 * 128 * 36 * 4;   // 73728 (double buffer)
    cudaFuncSetAttribute(gemm_db<0>, cudaFuncAttributeMaxDynamicSharedMemorySize, GEMM_SMEM);
    cudaFuncSetAttribute(gemm_db<3>, cudaFuncAttributeMaxDynamicSharedMemorySize, GEMM_SMEM);

    dim3 thr(256);

    // Batched Q/K/V projections (grid.z = 0,1,2)
    gemm_db<0><<<dim3(Ec / 128, (Bc * Tc) / 128, 3), thr, GEMM_SMEM>>>(
        query, key, value, Wq, Wk, Wv, bq, bk, bv, nullptr);

    // Fused score + online softmax + P@V  (raw scores -> g_p, stats -> g_c)
    attn_fused<<<dim3(Tc / 64, Bc * Hc), dim3(128)>>>(am, kpm);

    // attn_max output
    headmax_kernel<<<dim3((unsigned)(((size_t)Bc * Tc * Sc / 4) / 256)), thr>>>(attn_max);

    // Output projection
    gemm_db<3><<<dim3(Ec / 128, (Bc * Tc) / 128, 1), thr, GEMM_SMEM>>>(
        po, nullptr, nullptr, Wo, nullptr, nullptr, bo, nullptr, nullptr, out);
}